// round 15
// baseline (speedup 1.0000x reference)
#include <cuda_runtime.h>
#include <cuda.h>
#include <cstdint>

// Izhikevich neuron simulation on GB300 — round 10: 1KB-row TMA pipeline.
// input:  [32, 2000, 512] fp32; output: concat(s, v, u), each [32, 2000, 512].
//
// Evidence across rounds: DRAM% tracks TMA box row width monotonically
// (128B rows -> 63%, 256B -> 64%, 512B -> 71%). This round: 1KB rows.
// 64 CTAs x 256 threads, 1 CTA/SM. Each CTA owns 256 consecutive neurons of
// one batch. All data moves via TMA; per-SM service ~60 B/cyc (within the
// per-SM L1tex/TMA path), so halving active SMs should be bandwidth-neutral
// while doubling DRAM burst contiguity.
//   - input: 3-deep SMEM ring (one mbarrier per slot), thread0 issues loads
//   - output: 2-deep ring x 3 streams, bulk_group wait guards slot reuse

#define BATCH    32
#define NSTEPS   2000
#define NNEUR    512
#define PLANE    (NSTEPS * NNEUR)
#define NTOT     (BATCH * PLANE)
#define NWIDE    256                  // neurons per CTA
#define CHUNK    20
#define NCHUNK   (NSTEPS / CHUNK)     // 100
#define IN_RING  3
#define OUT_RING 2
#define ROWB     (NWIDE * 4)          // 1024 bytes per timestep row
#define CHUNKB   (CHUNK * ROWB)       // 20480 bytes per chunk per stream

// SMEM layout (bytes)
#define SM_MBAR  0                    // IN_RING * 8
#define SM_IN    128
#define SM_OUT   (SM_IN + IN_RING * CHUNKB)
#define SM_TOTAL (SM_OUT + 3 * OUT_RING * CHUNKB)   // 184,448 B

// ---------------- PTX helpers ----------------
__device__ __forceinline__ uint32_t smem_u32(const void* p) {
    uint32_t a;
    asm("{ .reg .u64 t; cvta.to.shared.u64 t, %1; cvt.u32.u64 %0, t; }"
        : "=r"(a) : "l"(p));
    return a;
}
#define MBAR_INIT(addr, cnt) \
    asm volatile("mbarrier.init.shared.b64 [%0], %1;" :: "r"(addr), "r"(cnt) : "memory")
#define MBAR_EXPECT_TX(addr, bytes) \
    asm volatile("mbarrier.arrive.expect_tx.shared.b64 _, [%0], %1;" \
                 :: "r"(addr), "r"(bytes) : "memory")
#define MBAR_WAIT(addr, parity) do {                                         \
    asm volatile(                                                            \
        "{\n\t.reg .pred P;\n\t"                                             \
        "W_%=:\n\t"                                                          \
        "mbarrier.try_wait.parity.acquire.cta.shared::cta.b64 P, [%0], %1, 0x989680;\n\t" \
        "@P bra.uni D_%=;\n\t"                                               \
        "bra.uni W_%=;\n\t"                                                  \
        "D_%=:\n\t}"                                                         \
        :: "r"(addr), "r"(parity) : "memory");                               \
} while (0)
#define TMA_LOAD(smem, map, cx, cy, cz, mbar) \
    asm volatile("cp.async.bulk.tensor.3d.shared::cta.global.tile.mbarrier::complete_tx::bytes " \
                 "[%0], [%1, {%2, %3, %4}], [%5];" \
                 :: "r"(smem), "l"(map), "r"(cx), "r"(cy), "r"(cz), "r"(mbar) : "memory")
#define TMA_STORE(map, cx, cy, cz, smem) \
    asm volatile("cp.async.bulk.tensor.3d.global.shared::cta.tile.bulk_group " \
                 "[%0, {%1, %2, %3}], [%4];" \
                 :: "l"(map), "r"(cx), "r"(cy), "r"(cz), "r"(smem) : "memory")
#define TMA_COMMIT()      asm volatile("cp.async.bulk.commit_group;" ::: "memory")
#define TMA_WAIT(n)       asm volatile("cp.async.bulk.wait_group.read %0;" :: "n"(n) : "memory")
#define FENCE_ASYNC()     asm volatile("fence.proxy.async.shared::cta;" ::: "memory")

// ---------------- TMA kernel ----------------
__global__ __launch_bounds__(256, 1)
void izh_tma_kernel(const __grid_constant__ CUtensorMap m_in,
                    const __grid_constant__ CUtensorMap m_s,
                    const __grid_constant__ CUtensorMap m_v,
                    const __grid_constant__ CUtensorMap m_u)
{
    extern __shared__ char smem[];
    const uint32_t sb  = smem_u32(smem);
    const int      tx  = threadIdx.x;            // 0..255
    const int      bid = blockIdx.x;             // 0..63
    const int      b   = bid >> 1;               // batch
    const int      n0  = (bid & 1) * NWIDE;      // first neuron of tile

    if (tx == 0) {
        #pragma unroll
        for (int s = 0; s < IN_RING; ++s)
            MBAR_INIT(sb + SM_MBAR + s * 8, 1);
    }
    __syncthreads();                              // mbarriers visible
    if (tx == 0) {
        // prologue: fill the whole input ring
        #pragma unroll
        for (int s = 0; s < IN_RING; ++s) {
            MBAR_EXPECT_TX(sb + SM_MBAR + s * 8, CHUNKB);
            TMA_LOAD(sb + SM_IN + s * CHUNKB, &m_in, n0, s * CHUNK, b,
                     sb + SM_MBAR + s * 8);
        }
    }

    float v = -65.0f;
    float u = -13.0f;   // B * C

    int slot_in = 0, phase_in = 0, slot_out = 0;

    #pragma unroll 1
    for (int k = 0; k < NCHUNK; ++k) {
        // input chunk k ready? (acquire orders the LDS below)
        MBAR_WAIT(sb + SM_MBAR + slot_in * 8, phase_in);
        // output slot free? store group from chunk k-2 fully read out of SMEM.
        if (tx == 0) TMA_WAIT(OUT_RING - 1);
        __syncthreads();

        const float* __restrict__ pin =
            (const float*)(smem + SM_IN + slot_in * CHUNKB);
        float* __restrict__ po =
            (float*)(smem + SM_OUT + slot_out * 3 * CHUNKB);

        #pragma unroll
        for (int j = 0; j < CHUNK; ++j) {
            float i_t = pin[j * NWIDE + tx];
            // exact reference association order — do not reassociate
            float dv = (0.04f * v * v + 5.0f * v + 140.0f - u + i_t) * 0.5f;
            float du = (0.02f * (0.2f * v - u)) * 0.5f;
            v = v + dv;
            u = u + du;
            bool  fired = (v >= 30.0f);
            float s = fired ? 1.0f : 0.0f;
            v = fired ? -65.0f : v;
            u = fired ? u + 8.0f : u;
            po[                    j * NWIDE + tx] = s;
            po[    CHUNK * NWIDE + j * NWIDE + tx] = v;
            po[2 * CHUNK * NWIDE + j * NWIDE + tx] = u;
        }
        __syncthreads();                          // all STS done

        if (tx == 0) {
            const int kn = k + IN_RING;
            if (kn < NCHUNK) {   // refill the input slot we just consumed
                MBAR_EXPECT_TX(sb + SM_MBAR + slot_in * 8, CHUNKB);
                TMA_LOAD(sb + SM_IN + slot_in * CHUNKB, &m_in, n0, kn * CHUNK, b,
                         sb + SM_MBAR + slot_in * 8);
            }

            FENCE_ASYNC();   // order generic-proxy STS before async-proxy reads
            const uint32_t so = sb + SM_OUT + slot_out * 3 * CHUNKB;
            const int      ty = k * CHUNK;
            TMA_STORE(&m_s, n0, ty, b, so);
            TMA_STORE(&m_v, n0, ty, b, so + CHUNKB);
            TMA_STORE(&m_u, n0, ty, b, so + 2 * CHUNKB);
            TMA_COMMIT();
        }

        if (++slot_in == IN_RING) { slot_in = 0; phase_in ^= 1; }
        if (++slot_out == OUT_RING) slot_out = 0;
    }

    if (tx == 0) TMA_WAIT(0);   // drain outstanding store groups before exit
}

// ---------------- fallback (no driver entry point): round-2 style ----------------
__global__ __launch_bounds__(32, 8)
void izh_fallback_kernel(const float* __restrict__ in,
                         float* __restrict__ out_s,
                         float* __restrict__ out_v,
                         float* __restrict__ out_u)
{
    int tid = blockIdx.x * 32 + threadIdx.x;
    int b   = tid >> 9;
    int n   = tid & 511;
    const float* __restrict__ ip = in    + b * PLANE + n;
    float* __restrict__ sp       = out_s + b * PLANE + n;
    float* __restrict__ vp       = out_v + b * PLANE + n;
    float* __restrict__ up       = out_u + b * PLANE + n;

    float v = -65.0f, u = -13.0f;
    float cur[16];
    #pragma unroll
    for (int j = 0; j < 16; ++j) cur[j] = __ldcs(ip + j * NNEUR);
    ip += 16 * NNEUR;

    #pragma unroll 1
    for (int c = 0; c < (NSTEPS / 16) - 1; ++c) {
        float nxt[16];
        #pragma unroll
        for (int j = 0; j < 16; ++j) nxt[j] = __ldcs(ip + j * NNEUR);
        ip += 16 * NNEUR;
        #pragma unroll
        for (int j = 0; j < 16; ++j) {
            float i_t = cur[j];
            float dv = (0.04f * v * v + 5.0f * v + 140.0f - u + i_t) * 0.5f;
            float du = (0.02f * (0.2f * v - u)) * 0.5f;
            v = v + dv; u = u + du;
            bool fired = (v >= 30.0f);
            float s = fired ? 1.0f : 0.0f;
            v = fired ? -65.0f : v;
            u = fired ? u + 8.0f : u;
            __stcs(sp + j * NNEUR, s);
            __stcs(vp + j * NNEUR, v);
            __stcs(up + j * NNEUR, u);
        }
        sp += 16 * NNEUR; vp += 16 * NNEUR; up += 16 * NNEUR;
        #pragma unroll
        for (int j = 0; j < 16; ++j) cur[j] = nxt[j];
    }
    #pragma unroll
    for (int j = 0; j < 16; ++j) {
        float i_t = cur[j];
        float dv = (0.04f * v * v + 5.0f * v + 140.0f - u + i_t) * 0.5f;
        float du = (0.02f * (0.2f * v - u)) * 0.5f;
        v = v + dv; u = u + du;
        bool fired = (v >= 30.0f);
        float s = fired ? 1.0f : 0.0f;
        v = fired ? -65.0f : v;
        u = fired ? u + 8.0f : u;
        __stcs(sp + j * NNEUR, s);
        __stcs(vp + j * NNEUR, v);
        __stcs(up + j * NNEUR, u);
    }
}

// ---------------- host ----------------
typedef CUresult (*tmap_encode_fn)(
    CUtensorMap*, CUtensorMapDataType, cuuint32_t, void*,
    const cuuint64_t*, const cuuint64_t*, const cuuint32_t*, const cuuint32_t*,
    CUtensorMapInterleave, CUtensorMapSwizzle, CUtensorMapL2promotion,
    CUtensorMapFloatOOBfill);

static bool make_map(tmap_encode_fn fn, CUtensorMap* m, void* base)
{
    cuuint64_t dims[3]    = { NNEUR, NSTEPS, BATCH };
    cuuint64_t strides[2] = { (cuuint64_t)NNEUR * 4,
                              (cuuint64_t)NSTEPS * NNEUR * 4 };
    cuuint32_t box[3]     = { NWIDE, CHUNK, 1 };
    cuuint32_t es[3]      = { 1, 1, 1 };
    return fn(m, CU_TENSOR_MAP_DATA_TYPE_FLOAT32, 3, base,
              dims, strides, box, es,
              CU_TENSOR_MAP_INTERLEAVE_NONE, CU_TENSOR_MAP_SWIZZLE_NONE,
              CU_TENSOR_MAP_L2_PROMOTION_L2_256B,
              CU_TENSOR_MAP_FLOAT_OOB_FILL_NONE) == CUDA_SUCCESS;
}

extern "C" void kernel_launch(void* const* d_in, const int* in_sizes, int n_in,
                              void* d_out, int out_size)
{
    float* in  = (float*)d_in[0];
    float* out = (float*)d_out;

    void* p = nullptr;
    cudaDriverEntryPointQueryResult qr = cudaDriverEntryPointSuccess;
    cudaGetDriverEntryPointByVersion("cuTensorMapEncodeTiled", &p, 12000,
                                     cudaEnableDefault, &qr);
    if (p) {
        CUtensorMap m_in, m_s, m_v, m_u;
        tmap_encode_fn fn = (tmap_encode_fn)p;
        bool ok = make_map(fn, &m_in, in)
               && make_map(fn, &m_s,  out)
               && make_map(fn, &m_v,  out + NTOT)
               && make_map(fn, &m_u,  out + 2 * NTOT);
        if (ok) {
            cudaFuncSetAttribute(izh_tma_kernel,
                                 cudaFuncAttributeMaxDynamicSharedMemorySize,
                                 SM_TOTAL);
            izh_tma_kernel<<<64, 256, SM_TOTAL>>>(m_in, m_s, m_v, m_u);
            return;
        }
    }
    izh_fallback_kernel<<<512, 32>>>(in, out, out + NTOT, out + 2 * NTOT);
}

// round 16
// speedup vs baseline: 1.2324x; 1.2324x over previous
#include <cuda_runtime.h>
#include <cuda.h>
#include <cstdint>

// Izhikevich neuron simulation on GB300 — round 11: smoothed store issue.
// input:  [32, 2000, 512] fp32; output: concat(s, v, u), each [32, 2000, 512].
//
// Shape sweep result: 128 CTAs x 128 threads (512B TMA rows) is the peak
// (63% / 64% / 71% / 54% DRAM for 128B/256B/512B/1KB rows). This round keeps
// that shape and halves the store burst granularity: store boxes are 10 rows
// (5KB/stream) issued twice per chunk instead of 25-row monoliths, smoothing
// the chip-wide DRAM request stream that left 29% of DRAM cycles idle.
//   - input: 5-deep ring of 20-row boxes (one mbarrier per slot)
//   - output: 6 half-chunk subslots x 3 streams, wait_group 4 guards reuse

#define BATCH    32
#define NSTEPS   2000
#define NNEUR    512
#define PLANE    (NSTEPS * NNEUR)
#define NTOT     (BATCH * PLANE)
#define NWIDE    128                  // neurons per CTA
#define CHUNK    20
#define HALF     10
#define NCHUNK   (NSTEPS / CHUNK)     // 100
#define IN_RING  5
#define OUT_SUB  6                    // half-chunk output subslots
#define ROWB     (NWIDE * 4)          // 512 bytes per timestep row
#define INCHB    (CHUNK * ROWB)       // 10240 B per input slot
#define HSTRB    (HALF * ROWB)        // 5120 B per stream per half
#define OSUBB    (3 * HSTRB)          // 15360 B per output subslot

// SMEM layout (bytes)
#define SM_MBAR  0                    // IN_RING * 8
#define SM_IN    128
#define SM_OUT   (SM_IN + IN_RING * INCHB)          // 51328
#define SM_TOTAL (SM_OUT + OUT_SUB * OSUBB)         // 143,488 B

// ---------------- PTX helpers ----------------
__device__ __forceinline__ uint32_t smem_u32(const void* p) {
    uint32_t a;
    asm("{ .reg .u64 t; cvta.to.shared.u64 t, %1; cvt.u32.u64 %0, t; }"
        : "=r"(a) : "l"(p));
    return a;
}
#define MBAR_INIT(addr, cnt) \
    asm volatile("mbarrier.init.shared.b64 [%0], %1;" :: "r"(addr), "r"(cnt) : "memory")
#define MBAR_EXPECT_TX(addr, bytes) \
    asm volatile("mbarrier.arrive.expect_tx.shared.b64 _, [%0], %1;" \
                 :: "r"(addr), "r"(bytes) : "memory")
#define MBAR_WAIT(addr, parity) do {                                         \
    asm volatile(                                                            \
        "{\n\t.reg .pred P;\n\t"                                             \
        "W_%=:\n\t"                                                          \
        "mbarrier.try_wait.parity.acquire.cta.shared::cta.b64 P, [%0], %1, 0x989680;\n\t" \
        "@P bra.uni D_%=;\n\t"                                               \
        "bra.uni W_%=;\n\t"                                                  \
        "D_%=:\n\t}"                                                         \
        :: "r"(addr), "r"(parity) : "memory");                               \
} while (0)
#define TMA_LOAD(smem, map, cx, cy, cz, mbar) \
    asm volatile("cp.async.bulk.tensor.3d.shared::cta.global.tile.mbarrier::complete_tx::bytes " \
                 "[%0], [%1, {%2, %3, %4}], [%5];" \
                 :: "r"(smem), "l"(map), "r"(cx), "r"(cy), "r"(cz), "r"(mbar) : "memory")
#define TMA_STORE(map, cx, cy, cz, smem) \
    asm volatile("cp.async.bulk.tensor.3d.global.shared::cta.tile.bulk_group " \
                 "[%0, {%1, %2, %3}], [%4];" \
                 :: "l"(map), "r"(cx), "r"(cy), "r"(cz), "r"(smem) : "memory")
#define TMA_COMMIT()      asm volatile("cp.async.bulk.commit_group;" ::: "memory")
#define TMA_WAIT(n)       asm volatile("cp.async.bulk.wait_group.read %0;" :: "n"(n) : "memory")
#define FENCE_ASYNC()     asm volatile("fence.proxy.async.shared::cta;" ::: "memory")

// ---------------- TMA kernel ----------------
__global__ __launch_bounds__(128, 1)
void izh_tma_kernel(const __grid_constant__ CUtensorMap m_in,
                    const __grid_constant__ CUtensorMap m_s,
                    const __grid_constant__ CUtensorMap m_v,
                    const __grid_constant__ CUtensorMap m_u)
{
    extern __shared__ char smem[];
    const uint32_t sb  = smem_u32(smem);
    const int      tx  = threadIdx.x;            // 0..127
    const int      bid = blockIdx.x;             // 0..127
    const int      b   = bid >> 2;               // batch
    const int      n0  = (bid & 3) * NWIDE;      // first neuron of tile

    if (tx == 0) {
        #pragma unroll
        for (int s = 0; s < IN_RING; ++s)
            MBAR_INIT(sb + SM_MBAR + s * 8, 1);
    }
    __syncthreads();                              // mbarriers visible
    if (tx == 0) {
        // prologue: fill the whole input ring
        #pragma unroll
        for (int s = 0; s < IN_RING; ++s) {
            MBAR_EXPECT_TX(sb + SM_MBAR + s * 8, INCHB);
            TMA_LOAD(sb + SM_IN + s * INCHB, &m_in, n0, s * CHUNK, b,
                     sb + SM_MBAR + s * 8);
        }
    }

    float v = -65.0f;
    float u = -13.0f;   // B * C

    int slot_in = 0, phase_in = 0;

    #pragma unroll 1
    for (int k = 0; k < NCHUNK; ++k) {
        // input chunk k ready? (acquire orders the LDS below)
        MBAR_WAIT(sb + SM_MBAR + slot_in * 8, phase_in);
        // ensure the two output subslots we are about to fill are retired:
        // <=4 pending groups means groups (2k-6) and (2k-5) are done.
        if (tx == 0) TMA_WAIT(4);
        __syncthreads();

        const float* __restrict__ pin =
            (const float*)(smem + SM_IN + slot_in * INCHB);

        #pragma unroll 1
        for (int h = 0; h < 2; ++h) {
            const int sub = (2 * k + h) % OUT_SUB;
            float* __restrict__ po = (float*)(smem + SM_OUT + sub * OSUBB);

            #pragma unroll
            for (int j = 0; j < HALF; ++j) {
                float i_t = pin[(h * HALF + j) * NWIDE + tx];
                // exact reference association order — do not reassociate
                float dv = (0.04f * v * v + 5.0f * v + 140.0f - u + i_t) * 0.5f;
                float du = (0.02f * (0.2f * v - u)) * 0.5f;
                v = v + dv;
                u = u + du;
                bool  fired = (v >= 30.0f);
                float s = fired ? 1.0f : 0.0f;
                v = fired ? -65.0f : v;
                u = fired ? u + 8.0f : u;
                po[                j * NWIDE + tx] = s;
                po[    HALF*NWIDE + j * NWIDE + tx] = v;
                po[2 * HALF*NWIDE + j * NWIDE + tx] = u;
            }
            __syncthreads();                      // half published

            if (tx == 0) {
                FENCE_ASYNC();  // order generic-proxy STS before async reads
                const uint32_t so = sb + SM_OUT + sub * OSUBB;
                const int      ty = k * CHUNK + h * HALF;
                TMA_STORE(&m_s, n0, ty, b, so);
                TMA_STORE(&m_v, n0, ty, b, so + HSTRB);
                TMA_STORE(&m_u, n0, ty, b, so + 2 * HSTRB);
                TMA_COMMIT();

                if (h == 1) {   // whole input slot consumed -> refill
                    const int kn = k + IN_RING;
                    if (kn < NCHUNK) {
                        MBAR_EXPECT_TX(sb + SM_MBAR + slot_in * 8, INCHB);
                        TMA_LOAD(sb + SM_IN + slot_in * INCHB, &m_in,
                                 n0, kn * CHUNK, b, sb + SM_MBAR + slot_in * 8);
                    }
                }
            }
        }

        if (++slot_in == IN_RING) { slot_in = 0; phase_in ^= 1; }
    }

    if (tx == 0) TMA_WAIT(0);   // drain outstanding store groups before exit
}

// ---------------- fallback (no driver entry point): round-2 style ----------------
__global__ __launch_bounds__(32, 8)
void izh_fallback_kernel(const float* __restrict__ in,
                         float* __restrict__ out_s,
                         float* __restrict__ out_v,
                         float* __restrict__ out_u)
{
    int tid = blockIdx.x * 32 + threadIdx.x;
    int b   = tid >> 9;
    int n   = tid & 511;
    const float* __restrict__ ip = in    + b * PLANE + n;
    float* __restrict__ sp       = out_s + b * PLANE + n;
    float* __restrict__ vp       = out_v + b * PLANE + n;
    float* __restrict__ up       = out_u + b * PLANE + n;

    float v = -65.0f, u = -13.0f;
    float cur[16];
    #pragma unroll
    for (int j = 0; j < 16; ++j) cur[j] = __ldcs(ip + j * NNEUR);
    ip += 16 * NNEUR;

    #pragma unroll 1
    for (int c = 0; c < (NSTEPS / 16) - 1; ++c) {
        float nxt[16];
        #pragma unroll
        for (int j = 0; j < 16; ++j) nxt[j] = __ldcs(ip + j * NNEUR);
        ip += 16 * NNEUR;
        #pragma unroll
        for (int j = 0; j < 16; ++j) {
            float i_t = cur[j];
            float dv = (0.04f * v * v + 5.0f * v + 140.0f - u + i_t) * 0.5f;
            float du = (0.02f * (0.2f * v - u)) * 0.5f;
            v = v + dv; u = u + du;
            bool fired = (v >= 30.0f);
            float s = fired ? 1.0f : 0.0f;
            v = fired ? -65.0f : v;
            u = fired ? u + 8.0f : u;
            __stcs(sp + j * NNEUR, s);
            __stcs(vp + j * NNEUR, v);
            __stcs(up + j * NNEUR, u);
        }
        sp += 16 * NNEUR; vp += 16 * NNEUR; up += 16 * NNEUR;
        #pragma unroll
        for (int j = 0; j < 16; ++j) cur[j] = nxt[j];
    }
    #pragma unroll
    for (int j = 0; j < 16; ++j) {
        float i_t = cur[j];
        float dv = (0.04f * v * v + 5.0f * v + 140.0f - u + i_t) * 0.5f;
        float du = (0.02f * (0.2f * v - u)) * 0.5f;
        v = v + dv; u = u + du;
        bool fired = (v >= 30.0f);
        float s = fired ? 1.0f : 0.0f;
        v = fired ? -65.0f : v;
        u = fired ? u + 8.0f : u;
        __stcs(sp + j * NNEUR, s);
        __stcs(vp + j * NNEUR, v);
        __stcs(up + j * NNEUR, u);
    }
}

// ---------------- host ----------------
typedef CUresult (*tmap_encode_fn)(
    CUtensorMap*, CUtensorMapDataType, cuuint32_t, void*,
    const cuuint64_t*, const cuuint64_t*, const cuuint32_t*, const cuuint32_t*,
    CUtensorMapInterleave, CUtensorMapSwizzle, CUtensorMapL2promotion,
    CUtensorMapFloatOOBfill);

static bool make_map(tmap_encode_fn fn, CUtensorMap* m, void* base, int box_y)
{
    cuuint64_t dims[3]    = { NNEUR, NSTEPS, BATCH };
    cuuint64_t strides[2] = { (cuuint64_t)NNEUR * 4,
                              (cuuint64_t)NSTEPS * NNEUR * 4 };
    cuuint32_t box[3]     = { NWIDE, (cuuint32_t)box_y, 1 };
    cuuint32_t es[3]      = { 1, 1, 1 };
    return fn(m, CU_TENSOR_MAP_DATA_TYPE_FLOAT32, 3, base,
              dims, strides, box, es,
              CU_TENSOR_MAP_INTERLEAVE_NONE, CU_TENSOR_MAP_SWIZZLE_NONE,
              CU_TENSOR_MAP_L2_PROMOTION_L2_256B,
              CU_TENSOR_MAP_FLOAT_OOB_FILL_NONE) == CUDA_SUCCESS;
}

extern "C" void kernel_launch(void* const* d_in, const int* in_sizes, int n_in,
                              void* d_out, int out_size)
{
    float* in  = (float*)d_in[0];
    float* out = (float*)d_out;

    void* p = nullptr;
    cudaDriverEntryPointQueryResult qr = cudaDriverEntryPointSuccess;
    cudaGetDriverEntryPointByVersion("cuTensorMapEncodeTiled", &p, 12000,
                                     cudaEnableDefault, &qr);
    if (p) {
        CUtensorMap m_in, m_s, m_v, m_u;
        tmap_encode_fn fn = (tmap_encode_fn)p;
        bool ok = make_map(fn, &m_in, in,          CHUNK)   // load box: 20 rows
               && make_map(fn, &m_s,  out,         HALF)    // store boxes: 10 rows
               && make_map(fn, &m_v,  out + NTOT,  HALF)
               && make_map(fn, &m_u,  out + 2*NTOT, HALF);
        if (ok) {
            cudaFuncSetAttribute(izh_tma_kernel,
                                 cudaFuncAttributeMaxDynamicSharedMemorySize,
                                 SM_TOTAL);
            izh_tma_kernel<<<128, 128, SM_TOTAL>>>(m_in, m_s, m_v, m_u);
            return;
        }
    }
    izh_fallback_kernel<<<512, 32>>>(in, out, out + NTOT, out + 2 * NTOT);
}